// round 2
// baseline (speedup 1.0000x reference)
#include <cuda_runtime.h>
#include <cstddef>

#define KTOT 4096   // 64*64 (u,v) pairs

// Scratch: 2048 T-rows x 4096. Row map:
//   [0,128)    T1  (path 0e x 0e -> 0e)
//   [128,256)  T2  (1o x 1o -> 0e)
//   [256,640)  T3  (0e x 1o -> 1o), m = k*128 + b
//   [640,1024) T4  (1o x 0e -> 1o)
//   [1024,1408)T5  (1o x 1o -> 1e, cross product)
//   [1408,2048)T6  (1o x 1o -> 2e), 5 components
__device__ float g_T[2048 * 4096];

__global__ void precompute_T(const float* __restrict__ x1, const float* __restrict__ x2) {
    __shared__ float sa0[64], sb0[64], sa1[64 * 3], sb1[64 * 3];
    int b = blockIdx.x;
    int tid = threadIdx.x;
    if (tid < 64) {
        sa0[tid] = x1[b * 256 + tid];
        sb0[tid] = x2[b * 256 + tid];
    } else {
        int j = tid - 64;               // 0..191
        sa1[j] = x1[b * 256 + 64 + j];
        sb1[j] = x2[b * 256 + 64 + j];
    }
    __syncthreads();

    const float C1   = 0.011048543456039806f;   // 1/sqrt(8192)
    const float C2   = -0.0063788657f;          // -1/sqrt(3*8192)
    const float C5   = 0.011048543456039806f;   // 1/(64*sqrt(2)) == C1
    const float IS2  = 0.70710678118654752f;
    const float IS6  = 0.40824829046386302f;
    const float INV64 = 0.015625f;

    for (int uv = tid; uv < KTOT; uv += blockDim.x) {
        int u = uv >> 6, v = uv & 63;
        float a0 = sa0[u], b0 = sb0[v];
        float av[3], bv[3];
#pragma unroll
        for (int i = 0; i < 3; i++) { av[i] = sa1[u * 3 + i]; bv[i] = sb1[v * 3 + i]; }

        float* T = g_T + uv;
        T[(size_t)(0 + b) * KTOT]   = C1 * a0 * b0;
        T[(size_t)(128 + b) * KTOT] = C2 * (av[0] * bv[0] + av[1] * bv[1] + av[2] * bv[2]);
#pragma unroll
        for (int k = 0; k < 3; k++) {
            int k1 = (k + 1) % 3, k2 = (k + 2) % 3;
            T[(size_t)(256 + k * 128 + b) * KTOT]  = C1 * a0 * bv[k];
            T[(size_t)(640 + k * 128 + b) * KTOT]  = C1 * av[k] * b0;
            T[(size_t)(1024 + k * 128 + b) * KTOT] = -C5 * (av[k1] * bv[k2] - av[k2] * bv[k1]);
        }
        float q0 = IS2 * (av[0] * bv[2] + av[2] * bv[0]);
        float q1 = IS2 * (av[0] * bv[1] + av[1] * bv[0]);
        float q2 = IS6 * (2.0f * av[1] * bv[1] - av[0] * bv[0] - av[2] * bv[2]);
        float q3 = IS2 * (av[1] * bv[2] + av[2] * bv[1]);
        float q4 = IS2 * (av[2] * bv[2] - av[0] * bv[0]);
        T[(size_t)(1408 + 0 * 128 + b) * KTOT] = INV64 * q0;
        T[(size_t)(1408 + 1 * 128 + b) * KTOT] = INV64 * q1;
        T[(size_t)(1408 + 2 * 128 + b) * KTOT] = INV64 * q2;
        T[(size_t)(1408 + 3 * 128 + b) * KTOT] = INV64 * q3;
        T[(size_t)(1408 + 4 * 128 + b) * KTOT] = INV64 * q4;
    }
}

// Out[m, w] = sum_uv T[m,uv] * W[uv,w]   (optionally two (W,T) pairs summed)
// Output written at out[b*65536 + obase + w*ncomp + k] with m = k*128 + b.
template <int M, int TN, int RM, int RN>
__global__ void __launch_bounds__(256, 1)
gemm_tp(const float* __restrict__ Wa, const float* __restrict__ Wb,
        int trowA, int trowB,
        float* __restrict__ out, int N, int obase, int ncomp) {
    constexpr int KC = 16;
    __shared__ alignas(16) float sW[KC][TN];
    __shared__ alignas(16) float sT[KC][M];

    float acc[RM][RN];
#pragma unroll
    for (int i = 0; i < RM; i++)
#pragma unroll
        for (int j = 0; j < RN; j++) acc[i][j] = 0.0f;

    int tid = threadIdx.x;
    int tx = tid & 15, ty = tid >> 4;
    int n0 = blockIdx.x * TN;

    for (int pass = 0; pass < 2; pass++) {
        const float* W = pass ? Wb : Wa;
        if (!W) break;
        const float* T = g_T + (size_t)(pass ? trowB : trowA) * KTOT;

        for (int k0 = 0; k0 < KTOT; k0 += KC) {
            __syncthreads();
            // Load W tile (KC x TN), coalesced float4
            constexpr int WV = KC * TN / 4;
            for (int i = tid; i < WV; i += 256) {
                int kk = i / (TN / 4), c = i % (TN / 4);
                *(float4*)&sW[kk][c * 4] =
                    *(const float4*)&W[(size_t)(k0 + kk) * N + n0 + c * 4];
            }
            // Load T tile (M x KC in gmem) -> transposed to sT[kk][m]
            constexpr int TV = KC * M / 4;
            for (int i = tid; i < TV; i += 256) {
                int mr = i / (KC / 4), c = i % (KC / 4);
                float4 t4 = *(const float4*)&T[(size_t)mr * KTOT + k0 + c * 4];
                sT[c * 4 + 0][mr] = t4.x;
                sT[c * 4 + 1][mr] = t4.y;
                sT[c * 4 + 2][mr] = t4.z;
                sT[c * 4 + 3][mr] = t4.w;
            }
            __syncthreads();

#pragma unroll
            for (int kk = 0; kk < KC; kk++) {
                float wv[RN];
#pragma unroll
                for (int j = 0; j < RN; j++) wv[j] = sW[kk][tx * RN + j];
#pragma unroll
                for (int i = 0; i < RM; i++) {
                    float tv = sT[kk][ty * RM + i];
#pragma unroll
                    for (int j = 0; j < RN; j++)
                        acc[i][j] = fmaf(tv, wv[j], acc[i][j]);
                }
            }
        }
    }

#pragma unroll
    for (int i = 0; i < RM; i++) {
        int m = ty * RM + i;
        int bb = m & 127;
        int kc = m >> 7;
        size_t rb = (size_t)bb * 65536 + obase + kc;
#pragma unroll
        for (int j = 0; j < RN; j++) {
            int n = n0 + tx * RN + j;
            out[rb + (size_t)n * ncomp] = acc[i][j];
        }
    }
}

extern "C" void kernel_launch(void* const* d_in, const int* in_sizes, int n_in,
                              void* d_out, int out_size) {
    const float* x1 = (const float*)d_in[0];
    const float* x2 = (const float*)d_in[1];
    const float* w1 = (const float*)d_in[2];
    const float* w2 = (const float*)d_in[3];
    const float* w3 = (const float*)d_in[4];
    const float* w4 = (const float*)d_in[5];
    const float* w5 = (const float*)d_in[6];
    const float* w6 = (const float*)d_in[7];
    float* out = (float*)d_out;

    precompute_T<<<128, 256>>>(x1, x2);

    // o0: (w1,T1) + (w2,T2), M=128, N=8192, out base 0, ncomp 1
    gemm_tp<128, 64, 8, 4><<<8192 / 64, 256>>>(w1, w2, 0, 128, out, 8192, 0, 1);
    // o1: (w3,T3) + (w4,T4), M=384, N=8192, base 8192, ncomp 3
    gemm_tp<384, 32, 24, 2><<<8192 / 32, 256>>>(w3, w4, 256, 640, out, 8192, 8192, 3);
    // o1e: (w5,T5), M=384, N=4096, base 32768, ncomp 3
    gemm_tp<384, 32, 24, 2><<<4096 / 32, 256>>>(w5, nullptr, 1024, 0, out, 4096, 32768, 3);
    // o2e: (w6,T6), M=640, N=4096, base 45056, ncomp 5
    gemm_tp<640, 32, 40, 2><<<4096 / 32, 256>>>(w6, nullptr, 1408, 0, out, 4096, 45056, 5);
}

// round 4
// speedup vs baseline: 14.0666x; 14.0666x over previous
#include <cuda_runtime.h>
#include <cuda_fp16.h>
#include <cstdint>
#include <cstddef>

#define KTOT 4096

// T precomputed in fp16: 2048 rows x 4096 (u,v) cols.
__device__ __half g_T[2048 * KTOT];

__device__ __forceinline__ uint32_t smem_u32(const void* p) {
    uint32_t a;
    asm("{ .reg .u64 t; cvta.to.shared.u64 t, %1; cvt.u32.u64 %0, t; }" : "=r"(a) : "l"(p));
    return a;
}
#define CP_ASYNC16(dst, src) \
    asm volatile("cp.async.cg.shared.global [%0], [%1], 16;" :: "r"(dst), "l"(src) : "memory")
#define CP_COMMIT() asm volatile("cp.async.commit_group;" ::: "memory")
#define CP_WAIT(n)  asm volatile("cp.async.wait_group %0;" :: "n"(n) : "memory")
#define LDSM_X4(r, addr) \
    asm volatile("ldmatrix.sync.aligned.m8n8.x4.shared.b16 {%0,%1,%2,%3}, [%4];" \
        : "=r"((r)[0]), "=r"((r)[1]), "=r"((r)[2]), "=r"((r)[3]) : "r"(addr))
#define LDSM_X4_T(r, addr) \
    asm volatile("ldmatrix.sync.aligned.m8n8.x4.trans.shared.b16 {%0,%1,%2,%3}, [%4];" \
        : "=r"((r)[0]), "=r"((r)[1]), "=r"((r)[2]), "=r"((r)[3]) : "r"(addr))
#define MMA16816(d, a, b) \
    asm volatile("mma.sync.aligned.m16n8k16.row.col.f32.f16.f16.f32 " \
        "{%0,%1,%2,%3}, {%4,%5,%6,%7}, {%8,%9}, {%0,%1,%2,%3};" \
        : "+f"((d)[0]), "+f"((d)[1]), "+f"((d)[2]), "+f"((d)[3]) \
        : "r"((a)[0]), "r"((a)[1]), "r"((a)[2]), "r"((a)[3]), "r"((b)[0]), "r"((b)[1]))

// ---------------- precompute T (fp16) ----------------
__global__ void precompute_T(const float* __restrict__ x1, const float* __restrict__ x2) {
    __shared__ float sa0[64], sb0[64], sa1[192], sb1[192];
    int b = blockIdx.x, tid = threadIdx.x;
    if (tid < 64) { sa0[tid] = x1[b * 256 + tid]; sb0[tid] = x2[b * 256 + tid]; }
    else { int j = tid - 64; sa1[j] = x1[b * 256 + 64 + j]; sb1[j] = x2[b * 256 + 64 + j]; }
    __syncthreads();

    const float C1 = 0.011048543456039806f;    // 1/sqrt(8192)
    const float C2 = -0.0063788657f;           // -1/sqrt(3*8192)
    const float IS2 = 0.70710678118654752f;
    const float IS6 = 0.40824829046386302f;
    const float INV64 = 0.015625f;

    for (int uv = tid; uv < KTOT; uv += blockDim.x) {
        int u = uv >> 6, v = uv & 63;
        float a0 = sa0[u], b0 = sb0[v];
        float av[3], bv[3];
#pragma unroll
        for (int i = 0; i < 3; i++) { av[i] = sa1[u * 3 + i]; bv[i] = sb1[v * 3 + i]; }
        __half* T = g_T + uv;
        T[(size_t)(0 + b) * KTOT]   = __float2half_rn(C1 * a0 * b0);
        T[(size_t)(128 + b) * KTOT] = __float2half_rn(C2 * (av[0]*bv[0] + av[1]*bv[1] + av[2]*bv[2]));
#pragma unroll
        for (int k = 0; k < 3; k++) {
            int k1 = (k + 1) % 3, k2 = (k + 2) % 3;
            T[(size_t)(256 + k * 128 + b) * KTOT]  = __float2half_rn(C1 * a0 * bv[k]);
            T[(size_t)(640 + k * 128 + b) * KTOT]  = __float2half_rn(C1 * av[k] * b0);
            T[(size_t)(1024 + k * 128 + b) * KTOT] = __float2half_rn(-C1 * (av[k1]*bv[k2] - av[k2]*bv[k1]));
        }
        float q[5];
        q[0] = IS2 * (av[0]*bv[2] + av[2]*bv[0]);
        q[1] = IS2 * (av[0]*bv[1] + av[1]*bv[0]);
        q[2] = IS6 * (2.0f*av[1]*bv[1] - av[0]*bv[0] - av[2]*bv[2]);
        q[3] = IS2 * (av[1]*bv[2] + av[2]*bv[1]);
        q[4] = IS2 * (av[2]*bv[2] - av[0]*bv[0]);
#pragma unroll
        for (int k = 0; k < 5; k++)
            T[(size_t)(1408 + k * 128 + b) * KTOT] = __float2half_rn(INV64 * q[k]);
    }
}

// ---------------- HMMA GEMM ----------------
// smem (dynamic, bytes):
//   As   @0      : 2 stages x 128 rows x 80B (32 halves + 8 pad)   = 20480
//   B32  @20480  : 2 stages x 32 rows x 512B (128 fp32)            = 32768
//   B16  @53248  : 2 stages x 32 rows x 272B (128 halves + 8 pad)  = 17408
#define SM_A   0
#define SM_B32 20480
#define SM_B16 53248
#define SMEM_BYTES 70656
#define KC 32

__global__ void __launch_bounds__(256, 2)
tp_gemm(const float* __restrict__ w1, const float* __restrict__ w2,
        const float* __restrict__ w3, const float* __restrict__ w4,
        const float* __restrict__ w5, const float* __restrict__ w6,
        float* __restrict__ out) {
    extern __shared__ char smem[];
    uint32_t sb = smem_u32(smem);
    int tid = threadIdx.x, wid = tid >> 5, lane = tid & 31;
    int warpM = wid >> 2, warpN = wid & 3;

    // ---- decode work ----
    int bid = blockIdx.x;
    int npass, trow0, trow1 = 0, Ngrp, n0, obase, ncomp, kc;
    const float *Wa, *Wb = nullptr;
    if (bid < 64) {                 // o0: 1x64 tiles, w1+w2
        npass = 2; trow0 = 0; trow1 = 128; Wa = w1; Wb = w2;
        Ngrp = 8192; n0 = bid * 128; obase = 0; ncomp = 1; kc = 0;
    } else if (bid < 256) {         // o1: 3x64 tiles, w3+w4
        int r = bid - 64; int nt = r / 3, mt = r % 3;
        npass = 2; trow0 = 256 + mt * 128; trow1 = 640 + mt * 128; Wa = w3; Wb = w4;
        Ngrp = 8192; n0 = nt * 128; obase = 8192; ncomp = 3; kc = mt;
    } else if (bid < 352) {         // o1e: 3x32 tiles, w5
        int r = bid - 256; int nt = r / 3, mt = r % 3;
        npass = 1; trow0 = 1024 + mt * 128; Wa = w5;
        Ngrp = 4096; n0 = nt * 128; obase = 32768; ncomp = 3; kc = mt;
    } else {                        // o2e: 5x32 tiles, w6
        int r = bid - 352; int nt = r / 5, mt = r % 5;
        npass = 1; trow0 = 1408 + mt * 128; Wa = w6;
        Ngrp = 4096; n0 = nt * 128; obase = 45056; ncomp = 5; kc = mt;
    }
    int nch = npass * (KTOT / KC);  // 128 or 256

    // ---- async load of one chunk into stage s ----
    auto issue_chunk = [&](int chunk, int s) {
        int pass = chunk >> 7;
        int k0 = (chunk & 127) * KC;
        int trow = pass ? trow1 : trow0;
        const float* W = pass ? Wb : Wa;
        // A: 128 x 32 halves (512 x 16B)
#pragma unroll
        for (int it = 0; it < 2; it++) {
            int idx = tid + it * 256;
            int row = idx >> 2, c = idx & 3;
            const void* src = g_T + ((size_t)(trow + row) * KTOT + k0 + c * 8);
            CP_ASYNC16(sb + SM_A + s * 10240 + row * 80 + c * 16, src);
        }
        // W fp32: 32 x 128 (1024 x 16B)
#pragma unroll
        for (int it = 0; it < 4; it++) {
            int idx = tid + it * 256;
            int r = idx >> 5, c = idx & 31;
            const void* src = W + ((size_t)(k0 + r) * Ngrp + n0 + c * 4);
            CP_ASYNC16(sb + SM_B32 + s * 16384 + r * 512 + c * 16, src);
        }
        CP_COMMIT();
    };
    auto convert_B = [&](int s) {
#pragma unroll
        for (int it = 0; it < 4; it++) {
            int idx = tid + it * 256;
            int r = idx >> 5, c = idx & 31;
            float4 f = *(const float4*)(smem + SM_B32 + s * 16384 + r * 512 + c * 16);
            __half2 h0 = __floats2half2_rn(f.x, f.y);
            __half2 h1 = __floats2half2_rn(f.z, f.w);
            uint2 v; v.x = *(uint32_t*)&h0; v.y = *(uint32_t*)&h1;
            *(uint2*)(smem + SM_B16 + s * 8704 + r * 272 + c * 8) = v;
        }
    };

    float acc[4][4][4];
#pragma unroll
    for (int i = 0; i < 4; i++)
#pragma unroll
        for (int j = 0; j < 4; j++)
#pragma unroll
            for (int c = 0; c < 4; c++) acc[i][j][c] = 0.0f;

    // prologue
    issue_chunk(0, 0);
    issue_chunk(1, 1);
    CP_WAIT(1);
    __syncthreads();
    convert_B(0);
    __syncthreads();

    for (int i = 0; i < nch; i++) {
        int s = i & 1;
        uint32_t aBase = sb + SM_A + s * 10240;
        uint32_t bBase = sb + SM_B16 + s * 8704;
#pragma unroll
        for (int k16 = 0; k16 < 2; k16++) {
            uint32_t afr[4][4], bfr[2][4];
#pragma unroll
            for (int mi = 0; mi < 4; mi++)
                LDSM_X4(afr[mi], aBase + (warpM * 64 + mi * 16 + (lane & 15)) * 80
                                       + k16 * 32 + (lane >> 4) * 16);
#pragma unroll
            for (int ni = 0; ni < 2; ni++)
                LDSM_X4_T(bfr[ni], bBase + (k16 * 16 + (lane & 15)) * 272
                                        + (warpN * 32 + ni * 16 + (lane >> 4) * 8) * 2);
#pragma unroll
            for (int mi = 0; mi < 4; mi++)
#pragma unroll
                for (int j = 0; j < 4; j++)
                    MMA16816(acc[mi][j], afr[mi], &bfr[j >> 1][(j & 1) * 2]);
        }
        if (i + 1 < nch) {
            CP_WAIT(0);
            __syncthreads();
            convert_B((i + 1) & 1);
            if (i + 2 < nch) issue_chunk(i + 2, i & 1);
            __syncthreads();
        }
    }

    // ---- epilogue: acc -> out ----
#pragma unroll
    for (int mi = 0; mi < 4; mi++) {
        int r0 = warpM * 64 + mi * 16 + (lane >> 2);   // = batch index b
#pragma unroll
        for (int j = 0; j < 4; j++) {
            int n = n0 + warpN * 32 + j * 8 + (lane & 3) * 2;
            size_t b0 = (size_t)r0 * 65536 + obase + kc;
            size_t b1 = (size_t)(r0 + 8) * 65536 + obase + kc;
            out[b0 + (size_t)n * ncomp]       = acc[mi][j][0];
            out[b0 + (size_t)(n + 1) * ncomp] = acc[mi][j][1];
            out[b1 + (size_t)n * ncomp]       = acc[mi][j][2];
            out[b1 + (size_t)(n + 1) * ncomp] = acc[mi][j][3];
        }
    }
}

extern "C" void kernel_launch(void* const* d_in, const int* in_sizes, int n_in,
                              void* d_out, int out_size) {
    const float* x1 = (const float*)d_in[0];
    const float* x2 = (const float*)d_in[1];
    const float* w1 = (const float*)d_in[2];
    const float* w2 = (const float*)d_in[3];
    const float* w3 = (const float*)d_in[4];
    const float* w4 = (const float*)d_in[5];
    const float* w5 = (const float*)d_in[6];
    const float* w6 = (const float*)d_in[7];
    float* out = (float*)d_out;

    cudaFuncSetAttribute(tp_gemm, cudaFuncAttributeMaxDynamicSharedMemorySize, SMEM_BYTES);
    precompute_T<<<128, 256>>>(x1, x2);
    tp_gemm<<<512, 256, SMEM_BYTES>>>(w1, w2, w3, w4, w5, w6, out);
}